// round 3
// baseline (speedup 1.0000x reference)
#include <cuda_runtime.h>
#include <math.h>
#include <stdint.h>

#define NN 4096
#define DD 1024
#define HH 4096

// ---------------- scratch (no allocations allowed) ----------------
__device__ float g_q[(size_t)NN * HH];   // q, later reused as scores@v
__device__ float g_k[(size_t)NN * HH];   // k, later reused as ff1
__device__ float g_v[(size_t)NN * HH];   // v
__device__ float g_vT[(size_t)HH * NN];  // v transposed
__device__ float g_s[(size_t)NN * NN];   // scores
__device__ float g_t[(size_t)NN * DD];   // attn proj / ff2
__device__ float g_h[(size_t)NN * DD];   // h after first LN
__device__ float g_WqT[(size_t)HH * DD];
__device__ float g_WkT[(size_t)HH * DD];
__device__ float g_WvT[(size_t)HH * DD];
__device__ float g_WoT[(size_t)DD * HH];
__device__ float g_W1T[(size_t)HH * DD];
__device__ float g_W2T[(size_t)DD * HH];

__device__ __forceinline__ uint32_t f2tf32(float x) {
    uint32_t r;
    asm("cvt.rna.tf32.f32 %0, %1;" : "=r"(r) : "f"(x));
    return r;
}

__device__ __forceinline__ void mma_tf32(float* c, const uint32_t* a, uint32_t b0, uint32_t b1) {
    asm volatile(
        "mma.sync.aligned.m16n8k8.row.col.f32.tf32.tf32.f32 "
        "{%0,%1,%2,%3}, {%4,%5,%6,%7}, {%8,%9}, {%0,%1,%2,%3};"
        : "+f"(c[0]), "+f"(c[1]), "+f"(c[2]), "+f"(c[3])
        : "r"(a[0]), "r"(a[1]), "r"(a[2]), "r"(a[3]), "r"(b0), "r"(b1));
}

// ---------------- 32x32 tiled transpose: out[c][r] = in[r][c] --------------
__global__ __launch_bounds__(256) void transpose32(const float* __restrict__ in,
                                                   float* __restrict__ out,
                                                   int rows, int cols) {
    __shared__ float tile[32][33];
    int c0 = blockIdx.x * 32;
    int r0 = blockIdx.y * 32;
    int tx = threadIdx.x & 31;
    int ty = threadIdx.x >> 5;     // 0..7
#pragma unroll
    for (int i = 0; i < 4; i++) {
        int r = r0 + ty + i * 8;
        tile[ty + i * 8][tx] = in[(size_t)r * cols + c0 + tx];
    }
    __syncthreads();
#pragma unroll
    for (int i = 0; i < 4; i++) {
        int c = c0 + ty + i * 8;
        out[(size_t)c * rows + r0 + tx] = tile[tx][ty + i * 8];
    }
}

// ---------------- TF32 tensor-core GEMM (NT only) --------------------------
// C[M,N] = A[M,K] @ B^T, with B stored [N,K] row-major.
// Block tile 128x128x32, 256 threads = 8 warps in 4(M) x 2(N).
// Warp tile 32x64 via m16n8k8: 2 m-subtiles x 8 n-subtiles.
// Smem layout ("k-paired"): element (r, k) of a tile lives at
//   word = r*40 + pidx(k)*2 + half(k),   pidx = 4*(k>>3) + (k&3),  half = (k>>2)&1
// so the (kt, kt+4) operand pair of one mma is an aligned uint2 -> LDS.64,
// and row-stride 40 makes all fragment loads bank-conflict-free.
template<bool BIAS, bool RELU>
__global__ __launch_bounds__(256, 2) void tgemm(const float* __restrict__ A,
                                                const float* __restrict__ B,
                                                const float* __restrict__ bias,
                                                float* __restrict__ C,
                                                int M, int N, int K) {
    __shared__ uint32_t As[128 * 40];
    __shared__ uint32_t Bs[128 * 40];

    const int bm = blockIdx.y * 128;
    const int bn = blockIdx.x * 128;
    const int tid = threadIdx.x;
    const int lane = tid & 31;
    const int g = lane >> 2;     // 0..7
    const int t = lane & 3;      // 0..3
    const int warp = tid >> 5;
    const int wm = warp >> 1;    // 0..3
    const int wn = warp & 1;     // 0..1

    float acc[2][8][4];
#pragma unroll
    for (int mi = 0; mi < 2; mi++)
#pragma unroll
        for (int nj = 0; nj < 8; nj++)
#pragma unroll
            for (int e = 0; e < 4; e++) acc[mi][nj][e] = 0.0f;

    const int nchunks = K / 32;
    float4 ra[4], rb[4];

    // per-thread store coordinates (same for A and B tiles)
    // f = tid + l*256 ; row = f>>3 ; e = f&7 ; global col = 4e + j
    // smem word = row*40 + 8*(e>>1) + (e&1) + 2j
    // ---- prefetch chunk 0 ----
#pragma unroll
    for (int l = 0; l < 4; l++) {
        int f = tid + l * 256;
        int row = f >> 3;
        int c4 = (f & 7) * 4;
        ra[l] = *(const float4*)(A + (size_t)(bm + row) * K + c4);
        rb[l] = *(const float4*)(B + (size_t)(bn + row) * K + c4);
    }

    for (int c = 0; c < nchunks; c++) {
        // ---- store regs -> smem (tf32 convert, k-paired layout) ----
#pragma unroll
        for (int l = 0; l < 4; l++) {
            int f = tid + l * 256;
            int row = f >> 3;
            int e = f & 7;
            int base = row * 40 + 8 * (e >> 1) + (e & 1);
            As[base + 0] = f2tf32(ra[l].x);
            As[base + 2] = f2tf32(ra[l].y);
            As[base + 4] = f2tf32(ra[l].z);
            As[base + 6] = f2tf32(ra[l].w);
            Bs[base + 0] = f2tf32(rb[l].x);
            Bs[base + 2] = f2tf32(rb[l].y);
            Bs[base + 4] = f2tf32(rb[l].z);
            Bs[base + 6] = f2tf32(rb[l].w);
        }
        __syncthreads();

        // ---- prefetch next chunk (overlaps with mma below) ----
        if (c + 1 < nchunks) {
            int k0 = (c + 1) * 32;
#pragma unroll
            for (int l = 0; l < 4; l++) {
                int f = tid + l * 256;
                int row = f >> 3;
                int c4 = (f & 7) * 4;
                ra[l] = *(const float4*)(A + (size_t)(bm + row) * K + k0 + c4);
                rb[l] = *(const float4*)(B + (size_t)(bn + row) * K + k0 + c4);
            }
        }

        // ---- compute 4 k-steps of 8 ----
#pragma unroll
        for (int ks = 0; ks < 4; ks++) {
            const int koff = 8 * ks + 2 * t;
            uint32_t a[2][4];
#pragma unroll
            for (int mi = 0; mi < 2; mi++) {
                int m = wm * 32 + mi * 16 + g;
                uint2 lo = *(const uint2*)&As[m * 40 + koff];
                uint2 hi = *(const uint2*)&As[(m + 8) * 40 + koff];
                a[mi][0] = lo.x;   // (m,   kt)
                a[mi][1] = hi.x;   // (m+8, kt)
                a[mi][2] = lo.y;   // (m,   kt+4)
                a[mi][3] = hi.y;   // (m+8, kt+4)
            }
#pragma unroll
            for (int nj = 0; nj < 8; nj++) {
                int n = wn * 64 + nj * 8 + g;
                uint2 bb = *(const uint2*)&Bs[n * 40 + koff];
                mma_tf32(acc[0][nj], a[0], bb.x, bb.y);
                mma_tf32(acc[1][nj], a[1], bb.x, bb.y);
            }
        }
        __syncthreads();
    }

    // ---- epilogue ----
#pragma unroll
    for (int mi = 0; mi < 2; mi++) {
        int row0 = bm + wm * 32 + mi * 16 + g;
        int row1 = row0 + 8;
#pragma unroll
        for (int nj = 0; nj < 8; nj++) {
            int col = bn + wn * 64 + nj * 8 + 2 * t;
            float v0 = acc[mi][nj][0], v1 = acc[mi][nj][1];
            float v2 = acc[mi][nj][2], v3 = acc[mi][nj][3];
            if (BIAS) {
                float bb0 = bias[col], bb1 = bias[col + 1];
                v0 += bb0; v1 += bb1; v2 += bb0; v3 += bb1;
            }
            if (RELU) {
                v0 = fmaxf(v0, 0.0f); v1 = fmaxf(v1, 0.0f);
                v2 = fmaxf(v2, 0.0f); v3 = fmaxf(v3, 0.0f);
            }
            *(float2*)(C + (size_t)row0 * N + col) = make_float2(v0, v1);
            *(float2*)(C + (size_t)row1 * N + col) = make_float2(v2, v3);
        }
    }
}

// ---------------- block reduction helpers ----------------
__device__ __forceinline__ float block_reduce_max(float v) {
    __shared__ float sh[32];
    int lane = threadIdx.x & 31, w = threadIdx.x >> 5;
#pragma unroll
    for (int o = 16; o > 0; o >>= 1) v = fmaxf(v, __shfl_xor_sync(0xffffffffu, v, o));
    if (lane == 0) sh[w] = v;
    __syncthreads();
    if (threadIdx.x < 32) {
        float t = (lane < (int)(blockDim.x >> 5)) ? sh[lane] : -INFINITY;
#pragma unroll
        for (int o = 16; o > 0; o >>= 1) t = fmaxf(t, __shfl_xor_sync(0xffffffffu, t, o));
        if (lane == 0) sh[0] = t;
    }
    __syncthreads();
    float r = sh[0];
    __syncthreads();
    return r;
}

__device__ __forceinline__ float2 block_reduce_sum2(float a, float b) {
    __shared__ float sha[32], shb[32];
    int lane = threadIdx.x & 31, w = threadIdx.x >> 5;
#pragma unroll
    for (int o = 16; o > 0; o >>= 1) {
        a += __shfl_xor_sync(0xffffffffu, a, o);
        b += __shfl_xor_sync(0xffffffffu, b, o);
    }
    if (lane == 0) { sha[w] = a; shb[w] = b; }
    __syncthreads();
    if (threadIdx.x < 32) {
        int nw = (int)(blockDim.x >> 5);
        float ta = (lane < nw) ? sha[lane] : 0.0f;
        float tb = (lane < nw) ? shb[lane] : 0.0f;
#pragma unroll
        for (int o = 16; o > 0; o >>= 1) {
            ta += __shfl_xor_sync(0xffffffffu, ta, o);
            tb += __shfl_xor_sync(0xffffffffu, tb, o);
        }
        if (lane == 0) { sha[0] = ta; shb[0] = tb; }
    }
    __syncthreads();
    float2 r = make_float2(sha[0], shb[0]);
    __syncthreads();
    return r;
}

// ---------------- softmax over rows of length NN (in place) ----------------
__global__ __launch_bounds__(256) void softmax_rows(float* __restrict__ S) {
    const int row = blockIdx.x;
    float* p = S + (size_t)row * NN;
    const int tid = threadIdx.x;
    const int PER = NN / 256;   // 16
    float vals[PER];
    float mx = -INFINITY;
#pragma unroll
    for (int i = 0; i < PER; i++) {
        vals[i] = p[tid + i * 256];
        mx = fmaxf(mx, vals[i]);
    }
    mx = block_reduce_max(mx);
    float s = 0.0f;
#pragma unroll
    for (int i = 0; i < PER; i++) {
        vals[i] = __expf(vals[i] - mx);
        s += vals[i];
    }
    float2 r = block_reduce_sum2(s, 0.0f);
    float inv = 1.0f / r.x;
#pragma unroll
    for (int i = 0; i < PER; i++) p[tid + i * 256] = vals[i] * inv;
}

// ---------------- out = LayerNorm(x + res) * g + b  (rows of DD) ----------
__global__ __launch_bounds__(256) void add_layernorm(const float* __restrict__ x,
                                                     const float* __restrict__ res,
                                                     const float* __restrict__ gamma,
                                                     const float* __restrict__ beta,
                                                     float* __restrict__ out) {
    const int row = blockIdx.x;
    const int tid = threadIdx.x;
    const int PER = DD / 256;   // 4
    float vals[PER];
    float s = 0.0f, s2 = 0.0f;
#pragma unroll
    for (int i = 0; i < PER; i++) {
        int c = tid + i * 256;
        float v = x[(size_t)row * DD + c] + res[(size_t)row * DD + c];
        vals[i] = v;
        s += v;
        s2 += v * v;
    }
    float2 r = block_reduce_sum2(s, s2);
    float mu = r.x * (1.0f / DD);
    float var = r.y * (1.0f / DD) - mu * mu;
    float rstd = rsqrtf(var + 1e-5f);
#pragma unroll
    for (int i = 0; i < PER; i++) {
        int c = tid + i * 256;
        out[(size_t)row * DD + c] = (vals[i] - mu) * rstd * gamma[c] + beta[c];
    }
}

// ---------------- launch ----------------
extern "C" void kernel_launch(void* const* d_in, const int* in_sizes, int n_in,
                              void* d_out, int out_size) {
    const float* x   = (const float*)d_in[0];
    const float* Wq  = (const float*)d_in[1];
    const float* Wk  = (const float*)d_in[2];
    const float* Wv  = (const float*)d_in[3];
    const float* Wo  = (const float*)d_in[4];
    const float* W1  = (const float*)d_in[5];
    const float* b1  = (const float*)d_in[6];
    const float* W2  = (const float*)d_in[7];
    const float* b2  = (const float*)d_in[8];
    const float* g1  = (const float*)d_in[9];
    const float* be1 = (const float*)d_in[10];
    const float* g2  = (const float*)d_in[11];
    const float* be2 = (const float*)d_in[12];
    float* out = (float*)d_out;

    float *q, *k, *v, *vT, *s, *t, *h;
    float *WqT, *WkT, *WvT, *WoT, *W1T, *W2T;
    cudaGetSymbolAddress((void**)&q, g_q);
    cudaGetSymbolAddress((void**)&k, g_k);
    cudaGetSymbolAddress((void**)&v, g_v);
    cudaGetSymbolAddress((void**)&vT, g_vT);
    cudaGetSymbolAddress((void**)&s, g_s);
    cudaGetSymbolAddress((void**)&t, g_t);
    cudaGetSymbolAddress((void**)&h, g_h);
    cudaGetSymbolAddress((void**)&WqT, g_WqT);
    cudaGetSymbolAddress((void**)&WkT, g_WkT);
    cudaGetSymbolAddress((void**)&WvT, g_WvT);
    cudaGetSymbolAddress((void**)&WoT, g_WoT);
    cudaGetSymbolAddress((void**)&W1T, g_W1T);
    cudaGetSymbolAddress((void**)&W2T, g_W2T);
    float* av  = q;   // reuse q for scores@v
    float* ff1 = k;   // reuse k for relu(h@W1+b1)

    dim3 blk(256);
    dim3 grid_NH(HH / 128, NN / 128);   // 32 x 32
    dim3 grid_NNg(NN / 128, NN / 128);  // 32 x 32
    dim3 grid_ND(DD / 128, NN / 128);   // 8 x 32
    dim3 tgrid_DH(HH / 32, DD / 32);    // transpose [D,H] -> [H,D]
    dim3 tgrid_HD(DD / 32, HH / 32);    // transpose [H,D] -> [D,H]
    dim3 tgrid_NH(HH / 32, NN / 32);    // transpose [N,H] -> [H,N]

    // ---- weight transposes (so every GEMM is NT with B=[N,K] row-major) ----
    transpose32<<<tgrid_DH, blk>>>(Wq, WqT, DD, HH);
    transpose32<<<tgrid_DH, blk>>>(Wk, WkT, DD, HH);
    transpose32<<<tgrid_DH, blk>>>(Wv, WvT, DD, HH);
    transpose32<<<tgrid_HD, blk>>>(Wo, WoT, HH, DD);
    transpose32<<<tgrid_DH, blk>>>(W1, W1T, DD, HH);
    transpose32<<<tgrid_HD, blk>>>(W2, W2T, HH, DD);

    // q, k, v projections: [N,D]@[D,H]  (B = W^T [H,D])
    tgemm<false, false><<<grid_NH, blk>>>(x, WqT, nullptr, q, NN, HH, DD);
    tgemm<false, false><<<grid_NH, blk>>>(x, WkT, nullptr, k, NN, HH, DD);
    tgemm<false, false><<<grid_NH, blk>>>(x, WvT, nullptr, v, NN, HH, DD);

    // scores = q @ k^T : B = k [N,H] already [N,K]-shaped
    tgemm<false, false><<<grid_NNg, blk>>>(q, k, nullptr, s, NN, NN, HH);
    softmax_rows<<<NN, blk>>>(s);

    // av = scores @ v : B = v^T [H,N]
    transpose32<<<tgrid_NH, blk>>>(v, vT, NN, HH);
    tgemm<false, false><<<grid_NH, blk>>>(s, vT, nullptr, av, NN, HH, NN);

    // attn = av @ Wo : B = Wo^T [D,H]
    tgemm<false, false><<<grid_ND, blk>>>(av, WoT, nullptr, t, NN, DD, HH);

    // h = LN(x + attn)
    add_layernorm<<<NN, blk>>>(x, t, g1, be1, h);

    // ff1 = relu(h @ W1 + b1) : B = W1^T [H,D]
    tgemm<true, true><<<grid_NH, blk>>>(h, W1T, b1, ff1, NN, HH, DD);

    // ff2 = ff1 @ W2 + b2 : B = W2^T [D,H]
    tgemm<true, false><<<grid_ND, blk>>>(ff1, W2T, b2, t, NN, DD, HH);

    // out = LN(h + ff2)
    add_layernorm<<<NN, blk>>>(h, t, g2, be2, out);
}

// round 4
// speedup vs baseline: 1.1990x; 1.1990x over previous
#include <cuda_runtime.h>
#include <math.h>
#include <stdint.h>

#define NN 4096
#define DD 1024
#define HH 4096

// ---------------- scratch (no allocations allowed) ----------------
__device__ float g_q[(size_t)NN * HH];   // q, later reused as scores@v
__device__ float g_k[(size_t)NN * HH];   // k, later reused as ff1
__device__ float g_v[(size_t)NN * HH];   // v
__device__ float g_vT[(size_t)HH * NN];  // v transposed
__device__ float g_s[(size_t)NN * NN];   // scores
__device__ float g_t[(size_t)NN * DD];   // attn proj / ff2
__device__ float g_h[(size_t)NN * DD];   // h after first LN
__device__ float g_WqT[(size_t)HH * DD];
__device__ float g_WkT[(size_t)HH * DD];
__device__ float g_WvT[(size_t)HH * DD];
__device__ float g_WoT[(size_t)DD * HH];
__device__ float g_W1T[(size_t)HH * DD];
__device__ float g_W2T[(size_t)DD * HH];

__device__ __forceinline__ uint32_t f2tf32(float x) {
    uint32_t r;
    asm("cvt.rna.tf32.f32 %0, %1;" : "=r"(r) : "f"(x));
    return r;
}

__device__ __forceinline__ void mma_tf32(float* c, const uint32_t* a, uint32_t b0, uint32_t b1) {
    asm volatile(
        "mma.sync.aligned.m16n8k8.row.col.f32.tf32.tf32.f32 "
        "{%0,%1,%2,%3}, {%4,%5,%6,%7}, {%8,%9}, {%0,%1,%2,%3};"
        : "+f"(c[0]), "+f"(c[1]), "+f"(c[2]), "+f"(c[3])
        : "r"(a[0]), "r"(a[1]), "r"(a[2]), "r"(a[3]), "r"(b0), "r"(b1));
}

// ---------------- 32x32 tiled transpose: out[c][r] = in[r][c] --------------
__global__ __launch_bounds__(256) void transpose32(const float* __restrict__ in,
                                                   float* __restrict__ out,
                                                   int rows, int cols) {
    __shared__ float tile[32][33];
    int c0 = blockIdx.x * 32;
    int r0 = blockIdx.y * 32;
    int tx = threadIdx.x & 31;
    int ty = threadIdx.x >> 5;     // 0..7
#pragma unroll
    for (int i = 0; i < 4; i++) {
        int r = r0 + ty + i * 8;
        tile[ty + i * 8][tx] = in[(size_t)r * cols + c0 + tx];
    }
    __syncthreads();
#pragma unroll
    for (int i = 0; i < 4; i++) {
        int c = c0 + ty + i * 8;
        out[(size_t)c * rows + r0 + tx] = tile[tx][ty + i * 8];
    }
}

// ---------------- TF32 tensor-core GEMM (NT only) --------------------------
// C[M,N] = A[M,K] @ B^T, with B stored [N,K] row-major.
// Block tile 128x128x32, 256 threads = 8 warps in 4(M) x 2(N).
// Warp tile 32x64 via m16n8k8: 2 m-subtiles x 8 n-subtiles.
//
// Smem "quad" layout (row stride 40 words):
//   word(m,k) = m*40 + 8*(k>>3) + 4*((k&3)>>1) + 2*(k&1) + ((k>>2)&1)
// => operand pair (kt, kt+4) is an aligned uint2 (LDS.64, conflict-free
//    per half-warp), and each 8-k block of a row is two aligned uint4s
//    {a.x,b.x,a.y,b.y} / {a.z,b.z,a.w,b.w} (vectorized STS.128 stores).
// Two smem stages (ping-pong): one __syncthreads per k-chunk.
#define TILE_WORDS (128 * 40)
#define GEMM_SMEM_BYTES (2 * 2 * TILE_WORDS * 4)

template<bool BIAS, bool RELU>
__global__ __launch_bounds__(256, 2) void tgemm(const float* __restrict__ A,
                                                const float* __restrict__ B,
                                                const float* __restrict__ bias,
                                                float* __restrict__ C,
                                                int M, int N, int K) {
    extern __shared__ uint32_t dsmem[];

    const int bm = blockIdx.y * 128;
    const int bn = blockIdx.x * 128;
    const int tid = threadIdx.x;
    const int lane = tid & 31;
    const int g = lane >> 2;     // 0..7
    const int t = lane & 3;      // 0..3
    const int warp = tid >> 5;
    const int wm = warp >> 1;    // 0..3
    const int wn = warp & 1;     // 0..1

    float acc[2][8][4];
#pragma unroll
    for (int mi = 0; mi < 2; mi++)
#pragma unroll
        for (int nj = 0; nj < 8; nj++)
#pragma unroll
            for (int e = 0; e < 4; e++) acc[mi][nj][e] = 0.0f;

    const int nchunks = K / 32;

    // per-thread tile units: u = tid + l*256 ; row = u>>2 ; e' = u&3
    const int row0 = tid >> 2;           // l=0 row
    const int row1 = (tid + 256) >> 2;   // l=1 row
    const int ee0 = tid & 3;
    const int ee1 = (tid + 256) & 3;     // == ee0, but keep explicit

    float4 pa[2], pb[2];  // A tile: [l] -> (va, vb)
    float4 qa[2], qb[2];  // B tile

    // ---- prefetch chunk 0 ----
    {
        const float* Ar0 = A + (size_t)(bm + row0) * K + 8 * ee0;
        const float* Ar1 = A + (size_t)(bm + row1) * K + 8 * ee1;
        const float* Br0 = B + (size_t)(bn + row0) * K + 8 * ee0;
        const float* Br1 = B + (size_t)(bn + row1) * K + 8 * ee1;
        pa[0] = *(const float4*)(Ar0);     pb[0] = *(const float4*)(Ar0 + 4);
        pa[1] = *(const float4*)(Ar1);     pb[1] = *(const float4*)(Ar1 + 4);
        qa[0] = *(const float4*)(Br0);     qb[0] = *(const float4*)(Br0 + 4);
        qa[1] = *(const float4*)(Br1);     qb[1] = *(const float4*)(Br1 + 4);
    }

    for (int c = 0; c < nchunks; c++) {
        uint32_t* As = dsmem + (c & 1) * (2 * TILE_WORDS);
        uint32_t* Bs = As + TILE_WORDS;

        // ---- store regs -> smem stage (tf32 convert, quad layout) ----
#pragma unroll
        for (int l = 0; l < 2; l++) {
            int row = l ? row1 : row0;
            int e = l ? ee1 : ee0;
            uint32_t* p = As + row * 40 + 8 * e;
            uint4 q0 = make_uint4(f2tf32(pa[l].x), f2tf32(pb[l].x),
                                  f2tf32(pa[l].y), f2tf32(pb[l].y));
            uint4 q1 = make_uint4(f2tf32(pa[l].z), f2tf32(pb[l].z),
                                  f2tf32(pa[l].w), f2tf32(pb[l].w));
            *(uint4*)p = q0;
            *(uint4*)(p + 4) = q1;
            uint32_t* pB = Bs + row * 40 + 8 * e;
            uint4 r0 = make_uint4(f2tf32(qa[l].x), f2tf32(qb[l].x),
                                  f2tf32(qa[l].y), f2tf32(qb[l].y));
            uint4 r1 = make_uint4(f2tf32(qa[l].z), f2tf32(qb[l].z),
                                  f2tf32(qa[l].w), f2tf32(qb[l].w));
            *(uint4*)pB = r0;
            *(uint4*)(pB + 4) = r1;
        }
        __syncthreads();

        // ---- prefetch next chunk (overlaps with mma below) ----
        if (c + 1 < nchunks) {
            int k0 = (c + 1) * 32;
            const float* Ar0 = A + (size_t)(bm + row0) * K + k0 + 8 * ee0;
            const float* Ar1 = A + (size_t)(bm + row1) * K + k0 + 8 * ee1;
            const float* Br0 = B + (size_t)(bn + row0) * K + k0 + 8 * ee0;
            const float* Br1 = B + (size_t)(bn + row1) * K + k0 + 8 * ee1;
            pa[0] = *(const float4*)(Ar0);     pb[0] = *(const float4*)(Ar0 + 4);
            pa[1] = *(const float4*)(Ar1);     pb[1] = *(const float4*)(Ar1 + 4);
            qa[0] = *(const float4*)(Br0);     qb[0] = *(const float4*)(Br0 + 4);
            qa[1] = *(const float4*)(Br1);     qb[1] = *(const float4*)(Br1 + 4);
        }

        // ---- compute 4 k-steps of 8 ----
#pragma unroll
        for (int ks = 0; ks < 4; ks++) {
            const int koff = 8 * ks + 4 * (t >> 1) + 2 * (t & 1);
            uint32_t a[2][4];
#pragma unroll
            for (int mi = 0; mi < 2; mi++) {
                int m = wm * 32 + mi * 16 + g;
                uint2 lo = *(const uint2*)&As[m * 40 + koff];
                uint2 hi = *(const uint2*)&As[(m + 8) * 40 + koff];
                a[mi][0] = lo.x;   // (m,   kt)
                a[mi][1] = hi.x;   // (m+8, kt)
                a[mi][2] = lo.y;   // (m,   kt+4)
                a[mi][3] = hi.y;   // (m+8, kt+4)
            }
#pragma unroll
            for (int nj = 0; nj < 8; nj++) {
                int n = wn * 64 + nj * 8 + g;
                uint2 bb = *(const uint2*)&Bs[n * 40 + koff];
                mma_tf32(acc[0][nj], a[0], bb.x, bb.y);
                mma_tf32(acc[1][nj], a[1], bb.x, bb.y);
            }
        }
        // no second sync: next iteration writes the other stage; its
        // __syncthreads orders these reads before the stage is reused.
    }

    // ---- epilogue ----
#pragma unroll
    for (int mi = 0; mi < 2; mi++) {
        int r0 = bm + wm * 32 + mi * 16 + g;
        int r1 = r0 + 8;
#pragma unroll
        for (int nj = 0; nj < 8; nj++) {
            int col = bn + wn * 64 + nj * 8 + 2 * t;
            float v0 = acc[mi][nj][0], v1 = acc[mi][nj][1];
            float v2 = acc[mi][nj][2], v3 = acc[mi][nj][3];
            if (BIAS) {
                float bb0 = bias[col], bb1 = bias[col + 1];
                v0 += bb0; v1 += bb1; v2 += bb0; v3 += bb1;
            }
            if (RELU) {
                v0 = fmaxf(v0, 0.0f); v1 = fmaxf(v1, 0.0f);
                v2 = fmaxf(v2, 0.0f); v3 = fmaxf(v3, 0.0f);
            }
            *(float2*)(C + (size_t)r0 * N + col) = make_float2(v0, v1);
            *(float2*)(C + (size_t)r1 * N + col) = make_float2(v2, v3);
        }
    }
}

// ---------------- block reduction helpers ----------------
__device__ __forceinline__ float block_reduce_max(float v) {
    __shared__ float sh[32];
    int lane = threadIdx.x & 31, w = threadIdx.x >> 5;
#pragma unroll
    for (int o = 16; o > 0; o >>= 1) v = fmaxf(v, __shfl_xor_sync(0xffffffffu, v, o));
    if (lane == 0) sh[w] = v;
    __syncthreads();
    if (threadIdx.x < 32) {
        float t = (lane < (int)(blockDim.x >> 5)) ? sh[lane] : -INFINITY;
#pragma unroll
        for (int o = 16; o > 0; o >>= 1) t = fmaxf(t, __shfl_xor_sync(0xffffffffu, t, o));
        if (lane == 0) sh[0] = t;
    }
    __syncthreads();
    float r = sh[0];
    __syncthreads();
    return r;
}

__device__ __forceinline__ float2 block_reduce_sum2(float a, float b) {
    __shared__ float sha[32], shb[32];
    int lane = threadIdx.x & 31, w = threadIdx.x >> 5;
#pragma unroll
    for (int o = 16; o > 0; o >>= 1) {
        a += __shfl_xor_sync(0xffffffffu, a, o);
        b += __shfl_xor_sync(0xffffffffu, b, o);
    }
    if (lane == 0) { sha[w] = a; shb[w] = b; }
    __syncthreads();
    if (threadIdx.x < 32) {
        int nw = (int)(blockDim.x >> 5);
        float ta = (lane < nw) ? sha[lane] : 0.0f;
        float tb = (lane < nw) ? shb[lane] : 0.0f;
#pragma unroll
        for (int o = 16; o > 0; o >>= 1) {
            ta += __shfl_xor_sync(0xffffffffu, ta, o);
            tb += __shfl_xor_sync(0xffffffffu, tb, o);
        }
        if (lane == 0) { sha[0] = ta; shb[0] = tb; }
    }
    __syncthreads();
    float2 r = make_float2(sha[0], shb[0]);
    __syncthreads();
    return r;
}

// ---------------- softmax over rows of length NN (in place) ----------------
__global__ __launch_bounds__(256) void softmax_rows(float* __restrict__ S) {
    const int row = blockIdx.x;
    float* p = S + (size_t)row * NN;
    const int tid = threadIdx.x;
    const int PER = NN / 256;   // 16
    float vals[PER];
    float mx = -INFINITY;
#pragma unroll
    for (int i = 0; i < PER; i++) {
        vals[i] = p[tid + i * 256];
        mx = fmaxf(mx, vals[i]);
    }
    mx = block_reduce_max(mx);
    float s = 0.0f;
#pragma unroll
    for (int i = 0; i < PER; i++) {
        vals[i] = __expf(vals[i] - mx);
        s += vals[i];
    }
    float2 r = block_reduce_sum2(s, 0.0f);
    float inv = 1.0f / r.x;
#pragma unroll
    for (int i = 0; i < PER; i++) p[tid + i * 256] = vals[i] * inv;
}

// ---------------- out = LayerNorm(x + res) * g + b  (rows of DD) ----------
__global__ __launch_bounds__(256) void add_layernorm(const float* __restrict__ x,
                                                     const float* __restrict__ res,
                                                     const float* __restrict__ gamma,
                                                     const float* __restrict__ beta,
                                                     float* __restrict__ out) {
    const int row = blockIdx.x;
    const int tid = threadIdx.x;
    const int PER = DD / 256;   // 4
    float vals[PER];
    float s = 0.0f, s2 = 0.0f;
#pragma unroll
    for (int i = 0; i < PER; i++) {
        int c = tid + i * 256;
        float v = x[(size_t)row * DD + c] + res[(size_t)row * DD + c];
        vals[i] = v;
        s += v;
        s2 += v * v;
    }
    float2 r = block_reduce_sum2(s, s2);
    float mu = r.x * (1.0f / DD);
    float var = r.y * (1.0f / DD) - mu * mu;
    float rstd = rsqrtf(var + 1e-5f);
#pragma unroll
    for (int i = 0; i < PER; i++) {
        int c = tid + i * 256;
        out[(size_t)row * DD + c] = (vals[i] - mu) * rstd * gamma[c] + beta[c];
    }
}

// ---------------- launch ----------------
extern "C" void kernel_launch(void* const* d_in, const int* in_sizes, int n_in,
                              void* d_out, int out_size) {
    const float* x   = (const float*)d_in[0];
    const float* Wq  = (const float*)d_in[1];
    const float* Wk  = (const float*)d_in[2];
    const float* Wv  = (const float*)d_in[3];
    const float* Wo  = (const float*)d_in[4];
    const float* W1  = (const float*)d_in[5];
    const float* b1  = (const float*)d_in[6];
    const float* W2  = (const float*)d_in[7];
    const float* b2  = (const float*)d_in[8];
    const float* g1  = (const float*)d_in[9];
    const float* be1 = (const float*)d_in[10];
    const float* g2  = (const float*)d_in[11];
    const float* be2 = (const float*)d_in[12];
    float* out = (float*)d_out;

    float *q, *k, *v, *vT, *s, *t, *h;
    float *WqT, *WkT, *WvT, *WoT, *W1T, *W2T;
    cudaGetSymbolAddress((void**)&q, g_q);
    cudaGetSymbolAddress((void**)&k, g_k);
    cudaGetSymbolAddress((void**)&v, g_v);
    cudaGetSymbolAddress((void**)&vT, g_vT);
    cudaGetSymbolAddress((void**)&s, g_s);
    cudaGetSymbolAddress((void**)&t, g_t);
    cudaGetSymbolAddress((void**)&h, g_h);
    cudaGetSymbolAddress((void**)&WqT, g_WqT);
    cudaGetSymbolAddress((void**)&WkT, g_WkT);
    cudaGetSymbolAddress((void**)&WvT, g_WvT);
    cudaGetSymbolAddress((void**)&WoT, g_WoT);
    cudaGetSymbolAddress((void**)&W1T, g_W1T);
    cudaGetSymbolAddress((void**)&W2T, g_W2T);
    float* av  = q;   // reuse q for scores@v
    float* ff1 = k;   // reuse k for relu(h@W1+b1)

    // opt-in to 80KB dynamic smem for each tgemm instantiation
    cudaFuncSetAttribute(tgemm<false, false>,
                         cudaFuncAttributeMaxDynamicSharedMemorySize, GEMM_SMEM_BYTES);
    cudaFuncSetAttribute(tgemm<true, true>,
                         cudaFuncAttributeMaxDynamicSharedMemorySize, GEMM_SMEM_BYTES);
    cudaFuncSetAttribute(tgemm<true, false>,
                         cudaFuncAttributeMaxDynamicSharedMemorySize, GEMM_SMEM_BYTES);

    dim3 blk(256);
    dim3 grid_NH(HH / 128, NN / 128);   // 32 x 32
    dim3 grid_NNg(NN / 128, NN / 128);  // 32 x 32
    dim3 grid_ND(DD / 128, NN / 128);   // 8 x 32
    dim3 tgrid_DH(HH / 32, DD / 32);    // transpose [D,H] -> [H,D]
    dim3 tgrid_HD(DD / 32, HH / 32);    // transpose [H,D] -> [D,H]
    dim3 tgrid_NH(HH / 32, NN / 32);    // transpose [N,H] -> [H,N]

    // ---- weight transposes (so every GEMM is NT with B=[N,K] row-major) ----
    transpose32<<<tgrid_DH, blk>>>(Wq, WqT, DD, HH);
    transpose32<<<tgrid_DH, blk>>>(Wk, WkT, DD, HH);
    transpose32<<<tgrid_DH, blk>>>(Wv, WvT, DD, HH);
    transpose32<<<tgrid_HD, blk>>>(Wo, WoT, HH, DD);
    transpose32<<<tgrid_DH, blk>>>(W1, W1T, DD, HH);
    transpose32<<<tgrid_HD, blk>>>(W2, W2T, HH, DD);

    // q, k, v projections: [N,D]@[D,H]  (B = W^T [H,D])
    tgemm<false, false><<<grid_NH, blk, GEMM_SMEM_BYTES>>>(x, WqT, nullptr, q, NN, HH, DD);
    tgemm<false, false><<<grid_NH, blk, GEMM_SMEM_BYTES>>>(x, WkT, nullptr, k, NN, HH, DD);
    tgemm<false, false><<<grid_NH, blk, GEMM_SMEM_BYTES>>>(x, WvT, nullptr, v, NN, HH, DD);

    // scores = q @ k^T : B = k [N,H] already [N,K]-shaped
    tgemm<false, false><<<grid_NNg, blk, GEMM_SMEM_BYTES>>>(q, k, nullptr, s, NN, NN, HH);
    softmax_rows<<<NN, blk>>>(s);

    // av = scores @ v : B = v^T [H,N]
    transpose32<<<tgrid_NH, blk>>>(v, vT, NN, HH);
    tgemm<false, false><<<grid_NH, blk, GEMM_SMEM_BYTES>>>(s, vT, nullptr, av, NN, HH, NN);

    // attn = av @ Wo : B = Wo^T [D,H]
    tgemm<false, false><<<grid_ND, blk, GEMM_SMEM_BYTES>>>(av, WoT, nullptr, t, NN, DD, HH);

    // h = LN(x + attn)
    add_layernorm<<<NN, blk>>>(x, t, g1, be1, h);

    // ff1 = relu(h @ W1 + b1) : B = W1^T [H,D]
    tgemm<true, true><<<grid_NH, blk, GEMM_SMEM_BYTES>>>(h, W1T, b1, ff1, NN, HH, DD);

    // ff2 = ff1 @ W2 + b2 : B = W2^T [D,H]
    tgemm<true, false><<<grid_ND, blk, GEMM_SMEM_BYTES>>>(ff1, W2T, b2, t, NN, DD, HH);

    // out = LN(h + ff2)
    add_layernorm<<<NN, blk>>>(h, t, g2, be2, out);
}

// round 6
// speedup vs baseline: 1.4650x; 1.2218x over previous
#include <cuda_runtime.h>
#include <math.h>
#include <stdint.h>

#define NN 4096
#define DD 1024
#define HH 4096

// ---------------- scratch (no allocations allowed) ----------------
__device__ float g_q[(size_t)NN * HH];
__device__ float g_k[(size_t)NN * HH];
__device__ float g_v[(size_t)NN * HH];
__device__ float g_vT[(size_t)HH * NN];
__device__ float g_s[(size_t)NN * NN];
__device__ float g_t[(size_t)NN * DD];
__device__ float g_h[(size_t)NN * DD];
__device__ float g_hr[(size_t)NN * DD];
__device__ float g_xr[(size_t)NN * DD];
__device__ float g_WqT[(size_t)HH * DD];
__device__ float g_WkT[(size_t)HH * DD];
__device__ float g_WvT[(size_t)HH * DD];
__device__ float g_WoT[(size_t)DD * HH];
__device__ float g_W1T[(size_t)HH * DD];
__device__ float g_W2T[(size_t)DD * HH];

__device__ __forceinline__ uint32_t f2tf32(float x) {
    uint32_t r;
    asm("cvt.rna.tf32.f32 %0, %1;" : "=r"(r) : "f"(x));
    return r;
}
__device__ __forceinline__ float roundtf(float x) {
    return __uint_as_float(f2tf32(x));
}
__device__ __forceinline__ uint32_t smem_u32(const void* p) {
    uint32_t a;
    asm("{ .reg .u64 t; cvta.to.shared.u64 t, %1; cvt.u32.u64 %0, t; }"
        : "=r"(a) : "l"(p));
    return a;
}
__device__ __forceinline__ void mma_tf32(float* c, const uint32_t* a, uint32_t b0, uint32_t b1) {
    asm volatile(
        "mma.sync.aligned.m16n8k8.row.col.f32.tf32.tf32.f32 "
        "{%0,%1,%2,%3}, {%4,%5,%6,%7}, {%8,%9}, {%0,%1,%2,%3};"
        : "+f"(c[0]), "+f"(c[1]), "+f"(c[2]), "+f"(c[3])
        : "r"(a[0]), "r"(a[1]), "r"(a[2]), "r"(a[3]), "r"(b0), "r"(b1));
}

// ---------------- TF32 tensor-core GEMM (NT) --------------------------------
// C[M,N] = A[M,K] @ B^T ; A [M,K] (pre-rounded tf32 values), B [N,K].
// Block 128x128x32, 256 thr, warps 4(M)x2(N), warp tile 32x64.
// A tile: [m][k] stride 36 words, filled by cp.async.cg (16B chunks).
// B tile: quad layout, row stride 40 words:
//   word(n,k) = n*40 + 8*(k>>3) + 2*(k&3) + ((k>>2)&1)
//   -> b-frag (kt, kt+4) is an aligned uint2 (LDS.64).
#define AW (128 * 36)
#define BW (128 * 40)
#define STAGE_W (AW + BW)
#define GEMM_SMEM (2 * STAGE_W * 4)

template<bool BIAS, bool RELU, bool ROUND>
__global__ __launch_bounds__(256, 2) void tgemm(const float* __restrict__ A,
                                                const float* __restrict__ B,
                                                const float* __restrict__ bias,
                                                float* __restrict__ C,
                                                int M, int N, int K) {
    extern __shared__ uint32_t sm[];
    const uint32_t sbase = smem_u32(sm);
    const int tid = threadIdx.x;
    const int lane = tid & 31;
    const int g = lane >> 2;
    const int t = lane & 3;
    const int warp = tid >> 5;
    const int wm = warp >> 1;
    const int wn = warp & 1;
    const int bm = blockIdx.y * 128;
    const int bn = blockIdx.x * 128;

    float acc[2][8][4];
#pragma unroll
    for (int mi = 0; mi < 2; mi++)
#pragma unroll
        for (int nj = 0; nj < 8; nj++)
#pragma unroll
            for (int e = 0; e < 4; e++) acc[mi][nj][e] = 0.0f;

    const int nch = K / 32;
    const int be = tid & 3;              // B 8k-segment index
    float4 q0[2], q1[2];                 // B staging

    // ---- A cp.async issue for chunk c into stage base (byte addr) ----
    auto issueA = [&](int c, uint32_t a_stage_bytes) {
#pragma unroll
        for (int l = 0; l < 4; l++) {
            int f = tid + l * 256;       // 0..1023 : 16B chunk id
            int m = f >> 3;
            int qq = f & 7;
            const float* src = A + (size_t)(bm + m) * K + c * 32 + qq * 4;
            uint32_t dst = a_stage_bytes + (uint32_t)(m * 36 + qq * 4) * 4;
            asm volatile("cp.async.cg.shared.global [%0], [%1], 16;"
                         :: "r"(dst), "l"(src) : "memory");
        }
        asm volatile("cp.async.commit_group;" ::: "memory");
    };
    auto ldgB = [&](int c) {
#pragma unroll
        for (int l = 0; l < 2; l++) {
            int f = tid + l * 256;
            int row = f >> 2;
            const float* src = B + (size_t)(bn + row) * K + c * 32 + be * 8;
            q0[l] = *(const float4*)src;
            q1[l] = *(const float4*)(src + 4);
        }
    };

    issueA(0, sbase);
    ldgB(0);

    for (int c = 0; c < nch; c++) {
        const int s = c & 1;
        uint32_t* As = sm + s * STAGE_W;
        uint32_t* Bs = As + AW;

        asm volatile("cp.async.wait_group 0;" ::: "memory");

        // ---- store B chunk c (cvt + quad interleave), 4 STS.128/thread ----
#pragma unroll
        for (int l = 0; l < 2; l++) {
            int f = tid + l * 256;
            int row = f >> 2;
            uint32_t* p = Bs + row * 40 + be * 8;
            *(uint4*)p = make_uint4(f2tf32(q0[l].x), f2tf32(q1[l].x),
                                    f2tf32(q0[l].y), f2tf32(q1[l].y));
            *(uint4*)(p + 4) = make_uint4(f2tf32(q0[l].z), f2tf32(q1[l].z),
                                          f2tf32(q0[l].w), f2tf32(q1[l].w));
        }
        __syncthreads();

        if (c + 1 < nch) {
            issueA(c + 1, sbase + (uint32_t)((s ^ 1) * STAGE_W * 4));
            ldgB(c + 1);
        }

        // ---- compute 4 k-steps ----
#pragma unroll
        for (int ks = 0; ks < 4; ks++) {
            const int kt = ks * 8 + t;
            uint32_t a[2][4];
#pragma unroll
            for (int mi = 0; mi < 2; mi++) {
                int m = wm * 32 + mi * 16 + g;
                a[mi][0] = As[m * 36 + kt];
                a[mi][1] = As[(m + 8) * 36 + kt];
                a[mi][2] = As[m * 36 + kt + 4];
                a[mi][3] = As[(m + 8) * 36 + kt + 4];
            }
            const int koff = ks * 8 + 2 * t;
#pragma unroll
            for (int nj = 0; nj < 8; nj++) {
                int n = wn * 64 + nj * 8 + g;
                uint2 bb = *(const uint2*)&Bs[n * 40 + koff];
                mma_tf32(acc[0][nj], a[0], bb.x, bb.y);
                mma_tf32(acc[1][nj], a[1], bb.x, bb.y);
            }
        }
    }

    // ---- epilogue ----
#pragma unroll
    for (int mi = 0; mi < 2; mi++) {
        int r0 = bm + wm * 32 + mi * 16 + g;
        int r1 = r0 + 8;
#pragma unroll
        for (int nj = 0; nj < 8; nj++) {
            int col = bn + wn * 64 + nj * 8 + 2 * t;
            float v0 = acc[mi][nj][0], v1 = acc[mi][nj][1];
            float v2 = acc[mi][nj][2], v3 = acc[mi][nj][3];
            if (BIAS) {
                float bb0 = bias[col], bb1 = bias[col + 1];
                v0 += bb0; v1 += bb1; v2 += bb0; v3 += bb1;
            }
            if (RELU) {
                v0 = fmaxf(v0, 0.0f); v1 = fmaxf(v1, 0.0f);
                v2 = fmaxf(v2, 0.0f); v3 = fmaxf(v3, 0.0f);
            }
            if (ROUND) {
                v0 = roundtf(v0); v1 = roundtf(v1);
                v2 = roundtf(v2); v3 = roundtf(v3);
            }
            *(float2*)(C + (size_t)r0 * N + col) = make_float2(v0, v1);
            *(float2*)(C + (size_t)r1 * N + col) = make_float2(v2, v3);
        }
    }
}

// ---------------- elementwise tf32 rounding copy ----------------
__global__ __launch_bounds__(256) void round_tf32_vec(const float* __restrict__ in,
                                                      float* __restrict__ out, int n4) {
    int i = blockIdx.x * 256 + threadIdx.x;
    if (i < n4) {
        float4 v = ((const float4*)in)[i];
        v.x = roundtf(v.x); v.y = roundtf(v.y);
        v.z = roundtf(v.z); v.w = roundtf(v.w);
        ((float4*)out)[i] = v;
    }
}

// ---------------- 32x32 tiled transpose ----------------
__global__ __launch_bounds__(256) void transpose32(const float* __restrict__ in,
                                                   float* __restrict__ out,
                                                   int rows, int cols) {
    __shared__ float tile[32][33];
    int c0 = blockIdx.x * 32;
    int r0 = blockIdx.y * 32;
    int tx = threadIdx.x & 31;
    int ty = threadIdx.x >> 5;
#pragma unroll
    for (int i = 0; i < 4; i++) {
        int r = r0 + ty + i * 8;
        tile[ty + i * 8][tx] = in[(size_t)r * cols + c0 + tx];
    }
    __syncthreads();
#pragma unroll
    for (int i = 0; i < 4; i++) {
        int c = c0 + ty + i * 8;
        out[(size_t)c * rows + r0 + tx] = tile[tx][ty + i * 8];
    }
}

// ---------------- reductions ----------------
__device__ __forceinline__ float block_reduce_max(float v) {
    __shared__ float sh[32];
    int lane = threadIdx.x & 31, w = threadIdx.x >> 5;
#pragma unroll
    for (int o = 16; o > 0; o >>= 1) v = fmaxf(v, __shfl_xor_sync(0xffffffffu, v, o));
    if (lane == 0) sh[w] = v;
    __syncthreads();
    if (threadIdx.x < 32) {
        float t = (lane < (int)(blockDim.x >> 5)) ? sh[lane] : -INFINITY;
#pragma unroll
        for (int o = 16; o > 0; o >>= 1) t = fmaxf(t, __shfl_xor_sync(0xffffffffu, t, o));
        if (lane == 0) sh[0] = t;
    }
    __syncthreads();
    float r = sh[0];
    __syncthreads();
    return r;
}

__device__ __forceinline__ float2 block_reduce_sum2(float a, float b) {
    __shared__ float sha[32], shb[32];
    int lane = threadIdx.x & 31, w = threadIdx.x >> 5;
#pragma unroll
    for (int o = 16; o > 0; o >>= 1) {
        a += __shfl_xor_sync(0xffffffffu, a, o);
        b += __shfl_xor_sync(0xffffffffu, b, o);
    }
    if (lane == 0) { sha[w] = a; shb[w] = b; }
    __syncthreads();
    if (threadIdx.x < 32) {
        int nw = (int)(blockDim.x >> 5);
        float ta = (lane < nw) ? sha[lane] : 0.0f;
        float tb = (lane < nw) ? shb[lane] : 0.0f;
#pragma unroll
        for (int o = 16; o > 0; o >>= 1) {
            ta += __shfl_xor_sync(0xffffffffu, ta, o);
            tb += __shfl_xor_sync(0xffffffffu, tb, o);
        }
        if (lane == 0) { sha[0] = ta; shb[0] = tb; }
    }
    __syncthreads();
    float2 r = make_float2(sha[0], shb[0]);
    __syncthreads();
    return r;
}

// ---------------- softmax (writes tf32-rounded values) ----------------
__global__ __launch_bounds__(256) void softmax_rows(float* __restrict__ S) {
    const int row = blockIdx.x;
    float* p = S + (size_t)row * NN;
    const int tid = threadIdx.x;
    const int PER = NN / 256;
    float vals[PER];
    float mx = -INFINITY;
#pragma unroll
    for (int i = 0; i < PER; i++) {
        vals[i] = p[tid + i * 256];
        mx = fmaxf(mx, vals[i]);
    }
    mx = block_reduce_max(mx);
    float s = 0.0f;
#pragma unroll
    for (int i = 0; i < PER; i++) {
        vals[i] = __expf(vals[i] - mx);
        s += vals[i];
    }
    float2 r = block_reduce_sum2(s, 0.0f);
    float inv = 1.0f / r.x;
#pragma unroll
    for (int i = 0; i < PER; i++) p[tid + i * 256] = roundtf(vals[i] * inv);
}

// ---------------- out = LayerNorm(x + res)*g + b ; optional rounded copy ----
__global__ __launch_bounds__(256) void add_layernorm(const float* __restrict__ x,
                                                     const float* __restrict__ res,
                                                     const float* __restrict__ gamma,
                                                     const float* __restrict__ beta,
                                                     float* __restrict__ out,
                                                     float* __restrict__ outR) {
    const int row = blockIdx.x;
    const int tid = threadIdx.x;
    const int PER = DD / 256;
    float vals[PER];
    float s = 0.0f, s2 = 0.0f;
#pragma unroll
    for (int i = 0; i < PER; i++) {
        int c = tid + i * 256;
        float v = x[(size_t)row * DD + c] + res[(size_t)row * DD + c];
        vals[i] = v;
        s += v;
        s2 += v * v;
    }
    float2 r = block_reduce_sum2(s, s2);
    float mu = r.x * (1.0f / DD);
    float var = r.y * (1.0f / DD) - mu * mu;
    float rstd = rsqrtf(var + 1e-5f);
#pragma unroll
    for (int i = 0; i < PER; i++) {
        int c = tid + i * 256;
        float o = (vals[i] - mu) * rstd * gamma[c] + beta[c];
        out[(size_t)row * DD + c] = o;
        if (outR) outR[(size_t)row * DD + c] = roundtf(o);
    }
}

// ---------------- launch ----------------
extern "C" void kernel_launch(void* const* d_in, const int* in_sizes, int n_in,
                              void* d_out, int out_size) {
    const float* x   = (const float*)d_in[0];
    const float* Wq  = (const float*)d_in[1];
    const float* Wk  = (const float*)d_in[2];
    const float* Wv  = (const float*)d_in[3];
    const float* Wo  = (const float*)d_in[4];
    const float* W1  = (const float*)d_in[5];
    const float* b1  = (const float*)d_in[6];
    const float* W2  = (const float*)d_in[7];
    const float* b2  = (const float*)d_in[8];
    const float* g1  = (const float*)d_in[9];
    const float* be1 = (const float*)d_in[10];
    const float* g2  = (const float*)d_in[11];
    const float* be2 = (const float*)d_in[12];
    float* out = (float*)d_out;

    float *q, *k, *v, *vT, *s, *t, *h, *hr, *xr;
    float *WqT, *WkT, *WvT, *WoT, *W1T, *W2T;
    cudaGetSymbolAddress((void**)&q, g_q);
    cudaGetSymbolAddress((void**)&k, g_k);
    cudaGetSymbolAddress((void**)&v, g_v);
    cudaGetSymbolAddress((void**)&vT, g_vT);
    cudaGetSymbolAddress((void**)&s, g_s);
    cudaGetSymbolAddress((void**)&t, g_t);
    cudaGetSymbolAddress((void**)&h, g_h);
    cudaGetSymbolAddress((void**)&hr, g_hr);
    cudaGetSymbolAddress((void**)&xr, g_xr);
    cudaGetSymbolAddress((void**)&WqT, g_WqT);
    cudaGetSymbolAddress((void**)&WkT, g_WkT);
    cudaGetSymbolAddress((void**)&WvT, g_WvT);
    cudaGetSymbolAddress((void**)&WoT, g_WoT);
    cudaGetSymbolAddress((void**)&W1T, g_W1T);
    cudaGetSymbolAddress((void**)&W2T, g_W2T);
    float* av  = q;
    float* ff1 = k;

    cudaFuncSetAttribute(tgemm<false, false, true>,
                         cudaFuncAttributeMaxDynamicSharedMemorySize, GEMM_SMEM);
    cudaFuncSetAttribute(tgemm<false, false, false>,
                         cudaFuncAttributeMaxDynamicSharedMemorySize, GEMM_SMEM);
    cudaFuncSetAttribute(tgemm<true, true, true>,
                         cudaFuncAttributeMaxDynamicSharedMemorySize, GEMM_SMEM);
    cudaFuncSetAttribute(tgemm<true, false, false>,
                         cudaFuncAttributeMaxDynamicSharedMemorySize, GEMM_SMEM);

    dim3 blk(256);
    dim3 grid_NH(HH / 128, NN / 128);
    dim3 grid_NNg(NN / 128, NN / 128);
    dim3 grid_ND(DD / 128, NN / 128);
    dim3 tgrid_DH(HH / 32, DD / 32);
    dim3 tgrid_HD(DD / 32, HH / 32);
    dim3 tgrid_NH(HH / 32, NN / 32);

    // 1: rounded copy of x (GEMM A-operand)
    round_tf32_vec<<<(NN * DD / 4 + 255) / 256, blk>>>(x, xr, NN * DD / 4);
    // 2-4: weight transposes
    transpose32<<<tgrid_DH, blk>>>(Wq, WqT, DD, HH);
    transpose32<<<tgrid_DH, blk>>>(Wk, WkT, DD, HH);
    transpose32<<<tgrid_DH, blk>>>(Wv, WvT, DD, HH);
    // 5-7: projections (launch #6 = k-proj gets profiled by ncu -s 5 -c 1)
    tgemm<false, false, true><<<grid_NH, blk, GEMM_SMEM>>>(xr, WqT, nullptr, q, NN, HH, DD);
    tgemm<false, false, true><<<grid_NH, blk, GEMM_SMEM>>>(xr, WkT, nullptr, k, NN, HH, DD);
    tgemm<false, false, true><<<grid_NH, blk, GEMM_SMEM>>>(xr, WvT, nullptr, v, NN, HH, DD);

    // scores = q @ k^T (output feeds softmax, which rounds)
    tgemm<false, false, false><<<grid_NNg, blk, GEMM_SMEM>>>(q, k, nullptr, s, NN, NN, HH);
    softmax_rows<<<NN, blk>>>(s);

    // av = s @ v^T^T
    transpose32<<<tgrid_NH, blk>>>(v, vT, NN, HH);
    tgemm<false, false, true><<<grid_NH, blk, GEMM_SMEM>>>(s, vT, nullptr, av, NN, HH, NN);

    // attn = av @ Wo (full precision: feeds residual)
    transpose32<<<tgrid_HD, blk>>>(Wo, WoT, HH, DD);
    tgemm<false, false, false><<<grid_ND, blk, GEMM_SMEM>>>(av, WoT, nullptr, t, NN, DD, HH);

    // h = LN(x + attn), plus rounded copy hr
    add_layernorm<<<NN, blk>>>(x, t, g1, be1, h, hr);

    // ff1 = relu(hr-rounded gemm + b1), stored rounded
    transpose32<<<tgrid_DH, blk>>>(W1, W1T, DD, HH);
    tgemm<true, true, true><<<grid_NH, blk, GEMM_SMEM>>>(hr, W1T, b1, ff1, NN, HH, DD);

    // ff2 = ff1 @ W2 + b2 (full precision: feeds residual)
    transpose32<<<tgrid_HD, blk>>>(W2, W2T, HH, DD);
    tgemm<true, false, false><<<grid_ND, blk, GEMM_SMEM>>>(ff1, W2T, b2, t, NN, DD, HH);

    // out = LN(h + ff2)
    add_layernorm<<<NN, blk>>>(h, t, g2, be2, out, nullptr);
}

// round 8
// speedup vs baseline: 4.0982x; 2.7974x over previous
#include <cuda_runtime.h>
#include <cuda_fp16.h>
#include <math.h>
#include <stdint.h>

#define NN 4096
#define DD 1024
#define HH 4096

// ---------------- scratch (no allocations allowed) ----------------
__device__ __half g_qh[(size_t)NN * HH];
__device__ __half g_kh[(size_t)NN * HH];
__device__ __half g_vh[(size_t)NN * HH];
__device__ __half g_vTh[(size_t)HH * NN];
__device__ __half g_sh[(size_t)NN * NN];
__device__ float  g_s[(size_t)NN * NN];
__device__ float  g_t[(size_t)NN * DD];
__device__ float  g_h[(size_t)NN * DD];
__device__ __half g_hh[(size_t)NN * DD];
__device__ __half g_xh[(size_t)NN * DD];
__device__ __half g_WqTh[(size_t)HH * DD];
__device__ __half g_WkTh[(size_t)HH * DD];
__device__ __half g_WvTh[(size_t)HH * DD];
__device__ __half g_WoTh[(size_t)DD * HH];
__device__ __half g_W1Th[(size_t)HH * DD];
__device__ __half g_W2Th[(size_t)DD * HH];

__device__ __forceinline__ uint32_t smem_u32(const void* p) {
    uint32_t a;
    asm("{ .reg .u64 t; cvta.to.shared.u64 t, %1; cvt.u32.u64 %0, t; }"
        : "=r"(a) : "l"(p));
    return a;
}
__device__ __forceinline__ void ldsm_x4(uint32_t* r, uint32_t addr) {
    asm volatile("ldmatrix.sync.aligned.m8n8.x4.shared.b16 {%0,%1,%2,%3}, [%4];"
                 : "=r"(r[0]), "=r"(r[1]), "=r"(r[2]), "=r"(r[3]) : "r"(addr));
}
__device__ __forceinline__ void mma_f16(float* c, const uint32_t* a, uint32_t b0, uint32_t b1) {
    asm volatile(
        "mma.sync.aligned.m16n8k16.row.col.f32.f16.f16.f32 "
        "{%0,%1,%2,%3}, {%4,%5,%6,%7}, {%8,%9}, {%0,%1,%2,%3};"
        : "+f"(c[0]), "+f"(c[1]), "+f"(c[2]), "+f"(c[3])
        : "r"(a[0]), "r"(a[1]), "r"(a[2]), "r"(a[3]), "r"(b0), "r"(b1));
}

// ---------------- FP16 tensor-core GEMM (NT) --------------------------------
// C[M,N] = A[M,K] @ B^T ; A [M,K] half, B [N,K] half, row-major.
// Block 128x128, K-chunk 64. 256 thr = 8 warps (4M x 2N), warp tile 32x64.
// smem per stage: A 128x128B (SW128) + B same = 32KB; 2 stages = 64KB.
// B fragments via NON-trans ldmatrix: with B stored [n][k], lane l receives
// (n = l>>2, k = (l&3)*2+{0,1}) which is exactly the mma row.col B fragment.
#define STAGE_B 32768
#define GEMM_SMEM (2 * STAGE_B)

template<bool BIAS, bool RELU, bool OUTH>
__global__ __launch_bounds__(256, 2) void hgemm(const __half* __restrict__ A,
                                                const __half* __restrict__ B,
                                                const float* __restrict__ bias,
                                                void* __restrict__ Cv,
                                                int M, int N, int K) {
    extern __shared__ char smem[];
    const uint32_t sbase = smem_u32(smem);
    const int tid = threadIdx.x;
    const int lane = tid & 31;
    const int g = lane >> 2;
    const int t = lane & 3;
    const int warp = tid >> 5;
    const int wm = warp >> 1;
    const int wn = warp & 1;
    const int bm = blockIdx.y * 128;
    const int bn = blockIdx.x * 128;

    float acc[2][8][4];
#pragma unroll
    for (int mi = 0; mi < 2; mi++)
#pragma unroll
        for (int nj = 0; nj < 8; nj++)
#pragma unroll
            for (int e = 0; e < 4; e++) acc[mi][nj][e] = 0.0f;

    const int nch = K / 64;

    // cp.async fill: f = tid + l*256 ; row = f>>3 ; seg = f&7 (16B units)
    auto issueAB = [&](int c) {
#pragma unroll
        for (int l = 0; l < 4; l++) {
            int f = tid + l * 256;
            int row = f >> 3;
            int seg = f & 7;
            uint32_t sw = (uint32_t)(row * 128 + ((seg ^ (row & 7)) << 4));
            uint32_t stage = sbase + (uint32_t)((c & 1) * STAGE_B);
            const __half* sa = A + (size_t)(bm + row) * K + c * 64 + seg * 8;
            const __half* sb = B + (size_t)(bn + row) * K + c * 64 + seg * 8;
            asm volatile("cp.async.cg.shared.global [%0], [%1], 16;"
                         :: "r"(stage + sw), "l"(sa) : "memory");
            asm volatile("cp.async.cg.shared.global [%0], [%1], 16;"
                         :: "r"(stage + 16384 + sw), "l"(sb) : "memory");
        }
        asm volatile("cp.async.commit_group;" ::: "memory");
    };

    // ldmatrix lane addressing (within-stage offsets)
    const int lan7 = lane & 7;
    const int m_loc0 = wm * 32 + lan7 + ((lane >> 3) & 1) * 8;   // mi adds 16
    const int a_seghi = lane >> 4;                                // 0/1
    const int n_base = wn * 64 + lan7 + ((lane >> 4) << 3);       // p adds 16
    const int b_seghi = (lane >> 3) & 1;

    issueAB(0);

    for (int c = 0; c < nch; c++) {
        asm volatile("cp.async.wait_group 0;" ::: "memory");
        __syncthreads();
        if (c + 1 < nch) issueAB(c + 1);

        const uint32_t a_st = sbase + (uint32_t)((c & 1) * STAGE_B);
        const uint32_t b_st = a_st + 16384;

#pragma unroll
        for (int ks = 0; ks < 4; ks++) {
            uint32_t a[2][4];
#pragma unroll
            for (int mi = 0; mi < 2; mi++) {
                int m = m_loc0 + mi * 16;
                uint32_t addr = a_st + m * 128 +
                                (((2 * ks + a_seghi) ^ lan7) << 4);
                ldsm_x4(a[mi], addr);
            }
#pragma unroll
            for (int p = 0; p < 4; p++) {
                uint32_t bb[4];
                int n = n_base + p * 16;
                uint32_t addr = b_st + n * 128 +
                                (((2 * ks + b_seghi) ^ lan7) << 4);
                ldsm_x4(bb, addr);
                mma_f16(acc[0][2 * p], a[0], bb[0], bb[1]);
                mma_f16(acc[1][2 * p], a[1], bb[0], bb[1]);
                mma_f16(acc[0][2 * p + 1], a[0], bb[2], bb[3]);
                mma_f16(acc[1][2 * p + 1], a[1], bb[2], bb[3]);
            }
        }
    }

    // ---- epilogue ----
#pragma unroll
    for (int mi = 0; mi < 2; mi++) {
        int r0 = bm + wm * 32 + mi * 16 + g;
        int r1 = r0 + 8;
#pragma unroll
        for (int nj = 0; nj < 8; nj++) {
            int col = bn + wn * 64 + nj * 8 + 2 * t;
            float v0 = acc[mi][nj][0], v1 = acc[mi][nj][1];
            float v2 = acc[mi][nj][2], v3 = acc[mi][nj][3];
            if (BIAS) {
                float bb0 = bias[col], bb1 = bias[col + 1];
                v0 += bb0; v1 += bb1; v2 += bb0; v3 += bb1;
            }
            if (RELU) {
                v0 = fmaxf(v0, 0.0f); v1 = fmaxf(v1, 0.0f);
                v2 = fmaxf(v2, 0.0f); v3 = fmaxf(v3, 0.0f);
            }
            if (OUTH) {
                __half2* C = (__half2*)Cv;
                C[((size_t)r0 * N + col) >> 1] = __floats2half2_rn(v0, v1);
                C[((size_t)r1 * N + col) >> 1] = __floats2half2_rn(v2, v3);
            } else {
                float* C = (float*)Cv;
                *(float2*)(C + (size_t)r0 * N + col) = make_float2(v0, v1);
                *(float2*)(C + (size_t)r1 * N + col) = make_float2(v2, v3);
            }
        }
    }
}

// ---------------- conversions / transposes ----------------
__global__ __launch_bounds__(256) void f2h_vec(const float* __restrict__ in,
                                               __half* __restrict__ out, int n4) {
    int i = blockIdx.x * 256 + threadIdx.x;
    if (i < n4) {
        float4 v = ((const float4*)in)[i];
        __half2 h0 = __floats2half2_rn(v.x, v.y);
        __half2 h1 = __floats2half2_rn(v.z, v.w);
        ((__half2*)out)[2 * i] = h0;
        ((__half2*)out)[2 * i + 1] = h1;
    }
}

// f32 in -> half out, transposed
__global__ __launch_bounds__(256) void transpose_f2h(const float* __restrict__ in,
                                                     __half* __restrict__ out,
                                                     int rows, int cols) {
    __shared__ float tile[32][33];
    int c0 = blockIdx.x * 32;
    int r0 = blockIdx.y * 32;
    int tx = threadIdx.x & 31;
    int ty = threadIdx.x >> 5;
#pragma unroll
    for (int i = 0; i < 4; i++) {
        int r = r0 + ty + i * 8;
        tile[ty + i * 8][tx] = in[(size_t)r * cols + c0 + tx];
    }
    __syncthreads();
#pragma unroll
    for (int i = 0; i < 4; i++) {
        int c = c0 + ty + i * 8;
        out[(size_t)c * rows + r0 + tx] = __float2half_rn(tile[tx][ty + i * 8]);
    }
}

// half in -> half out, transposed
__global__ __launch_bounds__(256) void transpose_h2h(const __half* __restrict__ in,
                                                     __half* __restrict__ out,
                                                     int rows, int cols) {
    __shared__ __half tile[32][33];
    int c0 = blockIdx.x * 32;
    int r0 = blockIdx.y * 32;
    int tx = threadIdx.x & 31;
    int ty = threadIdx.x >> 5;
#pragma unroll
    for (int i = 0; i < 4; i++) {
        int r = r0 + ty + i * 8;
        tile[ty + i * 8][tx] = in[(size_t)r * cols + c0 + tx];
    }
    __syncthreads();
#pragma unroll
    for (int i = 0; i < 4; i++) {
        int c = c0 + ty + i * 8;
        out[(size_t)c * rows + r0 + tx] = tile[tx][ty + i * 8];
    }
}

// ---------------- reductions ----------------
__device__ __forceinline__ float block_reduce_max(float v) {
    __shared__ float sh[32];
    int lane = threadIdx.x & 31, w = threadIdx.x >> 5;
#pragma unroll
    for (int o = 16; o > 0; o >>= 1) v = fmaxf(v, __shfl_xor_sync(0xffffffffu, v, o));
    if (lane == 0) sh[w] = v;
    __syncthreads();
    if (threadIdx.x < 32) {
        float t = (lane < (int)(blockDim.x >> 5)) ? sh[lane] : -INFINITY;
#pragma unroll
        for (int o = 16; o > 0; o >>= 1) t = fmaxf(t, __shfl_xor_sync(0xffffffffu, t, o));
        if (lane == 0) sh[0] = t;
    }
    __syncthreads();
    float r = sh[0];
    __syncthreads();
    return r;
}

__device__ __forceinline__ float2 block_reduce_sum2(float a, float b) {
    __shared__ float sha[32], shb[32];
    int lane = threadIdx.x & 31, w = threadIdx.x >> 5;
#pragma unroll
    for (int o = 16; o > 0; o >>= 1) {
        a += __shfl_xor_sync(0xffffffffu, a, o);
        b += __shfl_xor_sync(0xffffffffu, b, o);
    }
    if (lane == 0) { sha[w] = a; shb[w] = b; }
    __syncthreads();
    if (threadIdx.x < 32) {
        int nw = (int)(blockDim.x >> 5);
        float ta = (lane < nw) ? sha[lane] : 0.0f;
        float tb = (lane < nw) ? shb[lane] : 0.0f;
#pragma unroll
        for (int o = 16; o > 0; o >>= 1) {
            ta += __shfl_xor_sync(0xffffffffu, ta, o);
            tb += __shfl_xor_sync(0xffffffffu, tb, o);
        }
        if (lane == 0) { sha[0] = ta; shb[0] = tb; }
    }
    __syncthreads();
    float2 r = make_float2(sha[0], shb[0]);
    __syncthreads();
    return r;
}

// ---------------- softmax: f32 in, half out ----------------
__global__ __launch_bounds__(256) void softmax_rows(const float* __restrict__ S,
                                                    __half* __restrict__ Sh) {
    const int row = blockIdx.x;
    const float* p = S + (size_t)row * NN;
    __half* ph = Sh + (size_t)row * NN;
    const int tid = threadIdx.x;
    const int PER = NN / 256;
    float vals[PER];
    float mx = -INFINITY;
#pragma unroll
    for (int i = 0; i < PER; i++) {
        vals[i] = p[tid + i * 256];
        mx = fmaxf(mx, vals[i]);
    }
    mx = block_reduce_max(mx);
    float s = 0.0f;
#pragma unroll
    for (int i = 0; i < PER; i++) {
        vals[i] = __expf(vals[i] - mx);
        s += vals[i];
    }
    float2 r = block_reduce_sum2(s, 0.0f);
    float inv = 1.0f / r.x;
#pragma unroll
    for (int i = 0; i < PER; i++) ph[tid + i * 256] = __float2half_rn(vals[i] * inv);
}

// ---------------- out = LayerNorm(x + res)*g + b (+ optional half copy) ----
__global__ __launch_bounds__(256) void add_layernorm(const float* __restrict__ x,
                                                     const float* __restrict__ res,
                                                     const float* __restrict__ gamma,
                                                     const float* __restrict__ beta,
                                                     float* __restrict__ out,
                                                     __half* __restrict__ outH) {
    const int row = blockIdx.x;
    const int tid = threadIdx.x;
    const int PER = DD / 256;
    float vals[PER];
    float s = 0.0f, s2 = 0.0f;
#pragma unroll
    for (int i = 0; i < PER; i++) {
        int c = tid + i * 256;
        float v = x[(size_t)row * DD + c] + res[(size_t)row * DD + c];
        vals[i] = v;
        s += v;
        s2 += v * v;
    }
    float2 r = block_reduce_sum2(s, s2);
    float mu = r.x * (1.0f / DD);
    float var = r.y * (1.0f / DD) - mu * mu;
    float rstd = rsqrtf(var + 1e-5f);
#pragma unroll
    for (int i = 0; i < PER; i++) {
        int c = tid + i * 256;
        float o = (vals[i] - mu) * rstd * gamma[c] + beta[c];
        out[(size_t)row * DD + c] = o;
        if (outH) outH[(size_t)row * DD + c] = __float2half_rn(o);
    }
}

// ---------------- launch ----------------
extern "C" void kernel_launch(void* const* d_in, const int* in_sizes, int n_in,
                              void* d_out, int out_size) {
    const float* x   = (const float*)d_in[0];
    const float* Wq  = (const float*)d_in[1];
    const float* Wk  = (const float*)d_in[2];
    const float* Wv  = (const float*)d_in[3];
    const float* Wo  = (const float*)d_in[4];
    const float* W1  = (const float*)d_in[5];
    const float* b1  = (const float*)d_in[6];
    const float* W2  = (const float*)d_in[7];
    const float* b2  = (const float*)d_in[8];
    const float* g1  = (const float*)d_in[9];
    const float* be1 = (const float*)d_in[10];
    const float* g2  = (const float*)d_in[11];
    const float* be2 = (const float*)d_in[12];
    float* out = (float*)d_out;

    __half *qh, *kh, *vh, *vTh, *sh, *hh, *xh;
    __half *WqTh, *WkTh, *WvTh, *WoTh, *W1Th, *W2Th;
    float *s, *t, *h;
    cudaGetSymbolAddress((void**)&qh, g_qh);
    cudaGetSymbolAddress((void**)&kh, g_kh);
    cudaGetSymbolAddress((void**)&vh, g_vh);
    cudaGetSymbolAddress((void**)&vTh, g_vTh);
    cudaGetSymbolAddress((void**)&sh, g_sh);
    cudaGetSymbolAddress((void**)&s, g_s);
    cudaGetSymbolAddress((void**)&t, g_t);
    cudaGetSymbolAddress((void**)&h, g_h);
    cudaGetSymbolAddress((void**)&hh, g_hh);
    cudaGetSymbolAddress((void**)&xh, g_xh);
    cudaGetSymbolAddress((void**)&WqTh, g_WqTh);
    cudaGetSymbolAddress((void**)&WkTh, g_WkTh);
    cudaGetSymbolAddress((void**)&WvTh, g_WvTh);
    cudaGetSymbolAddress((void**)&WoTh, g_WoTh);
    cudaGetSymbolAddress((void**)&W1Th, g_W1Th);
    cudaGetSymbolAddress((void**)&W2Th, g_W2Th);
    __half* avh  = qh;   // q dead after scores
    __half* ff1h = kh;   // k dead after scores

    cudaFuncSetAttribute(hgemm<false, false, true>,
                         cudaFuncAttributeMaxDynamicSharedMemorySize, GEMM_SMEM);
    cudaFuncSetAttribute(hgemm<false, false, false>,
                         cudaFuncAttributeMaxDynamicSharedMemorySize, GEMM_SMEM);
    cudaFuncSetAttribute(hgemm<true, true, true>,
                         cudaFuncAttributeMaxDynamicSharedMemorySize, GEMM_SMEM);
    cudaFuncSetAttribute(hgemm<true, false, false>,
                         cudaFuncAttributeMaxDynamicSharedMemorySize, GEMM_SMEM);

    dim3 blk(256);
    dim3 grid_NH(HH / 128, NN / 128);
    dim3 grid_NNg(NN / 128, NN / 128);
    dim3 grid_ND(DD / 128, NN / 128);
    dim3 tgrid_DH(HH / 32, DD / 32);
    dim3 tgrid_HD(DD / 32, HH / 32);
    dim3 tgrid_NHh(HH / 32, NN / 32);

    // 1: x -> half
    f2h_vec<<<(NN * DD / 4 + 255) / 256, blk>>>(x, xh, NN * DD / 4);
    // 2-4: QKV weight transposes (f32 -> half)
    transpose_f2h<<<tgrid_DH, blk>>>(Wq, WqTh, DD, HH);
    transpose_f2h<<<tgrid_DH, blk>>>(Wk, WkTh, DD, HH);
    transpose_f2h<<<tgrid_DH, blk>>>(Wv, WvTh, DD, HH);
    // 5-7: projections (launch #6 = k-proj profiled by ncu)
    hgemm<false, false, true><<<grid_NH, blk, GEMM_SMEM>>>(xh, WqTh, nullptr, qh, NN, HH, DD);
    hgemm<false, false, true><<<grid_NH, blk, GEMM_SMEM>>>(xh, WkTh, nullptr, kh, NN, HH, DD);
    hgemm<false, false, true><<<grid_NH, blk, GEMM_SMEM>>>(xh, WvTh, nullptr, vh, NN, HH, DD);

    // scores = q @ k^T (f32 out), softmax -> half
    hgemm<false, false, false><<<grid_NNg, blk, GEMM_SMEM>>>(qh, kh, nullptr, s, NN, NN, HH);
    softmax_rows<<<NN, blk>>>(s, sh);

    // av = softmax @ v  (B = v^T)
    transpose_h2h<<<tgrid_NHh, blk>>>(vh, vTh, NN, HH);
    hgemm<false, false, true><<<grid_NH, blk, GEMM_SMEM>>>(sh, vTh, nullptr, avh, NN, HH, NN);

    // attn = av @ Wo (f32: residual)
    transpose_f2h<<<tgrid_HD, blk>>>(Wo, WoTh, HH, DD);
    hgemm<false, false, false><<<grid_ND, blk, GEMM_SMEM>>>(avh, WoTh, nullptr, t, NN, DD, HH);

    // h = LN(x + attn) (+ half copy)
    add_layernorm<<<NN, blk>>>(x, t, g1, be1, h, hh);

    // ff1 = relu(h @ W1 + b1) -> half
    transpose_f2h<<<tgrid_DH, blk>>>(W1, W1Th, DD, HH);
    hgemm<true, true, true><<<grid_NH, blk, GEMM_SMEM>>>(hh, W1Th, b1, ff1h, NN, HH, DD);

    // ff2 = ff1 @ W2 + b2 (f32: residual)
    transpose_f2h<<<tgrid_HD, blk>>>(W2, W2Th, HH, DD);
    hgemm<true, false, false><<<grid_ND, blk, GEMM_SMEM>>>(ff1h, W2Th, b2, t, NN, DD, HH);

    // out = LN(h + ff2)
    add_layernorm<<<NN, blk>>>(h, t, g2, be2, out, nullptr);
}